// round 1
// baseline (speedup 1.0000x reference)
#include <cuda_runtime.h>
#include <math.h>

// Problem constants
#define NPROTO 256
#define NCH    256
#define NHW    4096
#define NBATCH 32
#define NT     64      // pixels per block tile
#define KT     32      // k (channel) chunk
#define ASTR   266     // padded smem row stride for A tile (protos)
#define QSTR   160     // Q dup tile row stride: 8 groups * 20 floats

// Scratch (static device globals — no allocation)
__device__ float g_protosN[NPROTO * NCH];
__device__ int   g_valid[NPROTO];

// ---------------------------------------------------------------------------
// Kernel 1: build normalized prototypes + validity mask.
// One block per proto p = s*64 + i*8 + j ; thread c = channel.
// ---------------------------------------------------------------------------
__global__ void proto_kernel(const float* __restrict__ sup_x,
                             const float* __restrict__ sup_y) {
    __shared__ float sh[256];
    int p = blockIdx.x;
    int s = p >> 6, ij = p & 63, i = ij >> 3, j = ij & 7;
    int c = threadIdx.x;

    const float* base = sup_x + (((size_t)(s * 256 + c)) * 64 + i * 8) * 64 + j * 8;
    float sum = 0.f;
#pragma unroll
    for (int di = 0; di < 8; di++) {
        const float4* r = (const float4*)(base + di * 64);
        float4 a = r[0], b4 = r[1];
        sum += ((a.x + a.y) + (a.z + a.w)) + ((b4.x + b4.y) + (b4.z + b4.w));
    }
    float f = sum * (1.0f / 64.0f);

    // norm over channels
    sh[c] = f * f;
    __syncthreads();
    for (int st = 128; st > 0; st >>= 1) {
        if (c < st) sh[c] += sh[c + st];
        __syncthreads();
    }
    float nrm = sqrtf(sh[0]);
    float inv = 1.0f / fmaxf(nrm, 1e-4f);
    g_protosN[p * NCH + c] = f * inv;
    __syncthreads();

    // validity: mean of binary mask over the 8x8 block > 0.5
    float m = 0.f;
    if (c < 64) {
        int di = c >> 3, dj = c & 7;
        float y = sup_y[(size_t)s * 4096 + (i * 8 + di) * 64 + (j * 8 + dj)];
        m = (y > 0.95f) ? 1.f : 0.f;
    }
    sh[c] = m;
    __syncthreads();
    for (int st = 128; st > 0; st >>= 1) {
        if (c < st) sh[c] += sh[c + st];
        __syncthreads();
    }
    if (c == 0) g_valid[p] = (sh[0] * (1.0f / 64.0f) > 0.5f) ? 1 : 0;
}

// ---------------------------------------------------------------------------
// Kernel 2: proto_grid passthrough (output segment 3)
// ---------------------------------------------------------------------------
__global__ void grid_kernel(const float* __restrict__ sup_y, float* __restrict__ out) {
    int idx = blockIdx.x * 256 + threadIdx.x;
    if (idx < 16384)
        out[262144 + idx] = (sup_y[idx] > 0.95f) ? 1.f : 0.f;
}

// ---------------------------------------------------------------------------
// Packed f32x2 FMA (PTX-only path; ptxas never auto-fuses this)
// ---------------------------------------------------------------------------
__device__ __forceinline__ void ffma2(unsigned long long& d,
                                      unsigned long long a,
                                      unsigned long long b) {
    asm("fma.rn.f32x2 %0, %1, %2, %0;" : "+l"(d) : "l"(a), "l"(b));
}

// ---------------------------------------------------------------------------
// Kernel 3: fused GEMM + norm + masked softmax + argmax + pred
// grid = 32 batches * 64 pixel tiles ; block = 256 threads
// thread (ty,tx): protos [ty*8, ty*8+8) as 4 packed pairs; pixels [tx*8, tx*8+8)
// ---------------------------------------------------------------------------
__global__ void __launch_bounds__(256, 2)
dist_kernel(const float* __restrict__ qry, float* __restrict__ out) {
    extern __shared__ float sm[];
    float* As = sm;                     // KT * ASTR = 8512 floats
    float* Qs = sm + KT * ASTR;         // KT * QSTR = 5120 floats (dup'd q)
    float* dS = sm;                     // reused: 256*64 = 16384 floats
    float* ssq = sm + NPROTO * NT;      // 4*64 partial sum-of-squares
    float* gN  = ssq + 256;             // 64 qnorms
    float* rA  = gN + 64;               // 4*64 partial max
    int*   rI  = (int*)(rA + 256);      // 4*64 partial argmax
    float* rS  = (float*)(rI + 256);    // 4*64 partial sumexp
    float* rW  = rS + 256;              // 4*64 partial weighted sum
    float* gM  = rW + 256;              // 64 global max
    int*   gI  = (int*)(gM + 64);       // 64 global argmax

    int tid = threadIdx.x;
    int b  = blockIdx.x >> 6;
    int n0 = (blockIdx.x & 63) << 6;
    const float* Qb = qry + (size_t)b * NCH * NHW + n0;

    int ty = tid >> 3, tx = tid & 7;    // compute mapping
    int ln = tid & 63, lk = tid >> 6;   // load/reduce mapping

    unsigned long long acc[4][8];
#pragma unroll
    for (int a = 0; a < 4; a++)
#pragma unroll
        for (int nn = 0; nn < 8; nn++) acc[a][nn] = 0ull;

    float myssq = 0.f;
    const int qgrp = (ln >> 3) * 20 + (ln & 7) * 2;   // dup slot for pixel ln

    for (int ct = 0; ct < 8; ct++) {
        int c0 = ct * KT;
        __syncthreads();
        // Load A tile: As[kk][p] = protosN[p][c0+kk]  (coalesced on kk)
#pragma unroll 8
        for (int i = 0; i < 32; i++) {
            int f = tid + i * 256;
            int kk = f & 31, p = f >> 5;
            As[kk * ASTR + p] = g_protosN[p * NCH + c0 + kk];
        }
        // Load Q tile (duplicated pairs) + accumulate sum of squares
#pragma unroll
        for (int r = 0; r < 8; r++) {
            int k = lk + (r << 2);
            float v = Qb[(size_t)(c0 + k) * NHW + ln];
            myssq += v * v;
            float* q = &Qs[k * QSTR + qgrp];
            q[0] = v; q[1] = v;
        }
        __syncthreads();

        // Compute: 32 packed FMAs per k-step per thread
#pragma unroll 4
        for (int kk = 0; kk < KT; kk++) {
            const unsigned long long* ap =
                (const unsigned long long*)&As[kk * ASTR + ty * 8];
            unsigned long long aa0 = ap[0], aa1 = ap[1], aa2 = ap[2], aa3 = ap[3];
            const ulonglong2* qp = (const ulonglong2*)&Qs[kk * QSTR + tx * 20];
            ulonglong2 u0 = qp[0], u1 = qp[1], u2 = qp[2], u3 = qp[3];
            unsigned long long qd0 = u0.x, qd1 = u0.y, qd2 = u1.x, qd3 = u1.y;
            unsigned long long qd4 = u2.x, qd5 = u2.y, qd6 = u3.x, qd7 = u3.y;

            ffma2(acc[0][0], aa0, qd0); ffma2(acc[0][1], aa0, qd1);
            ffma2(acc[0][2], aa0, qd2); ffma2(acc[0][3], aa0, qd3);
            ffma2(acc[0][4], aa0, qd4); ffma2(acc[0][5], aa0, qd5);
            ffma2(acc[0][6], aa0, qd6); ffma2(acc[0][7], aa0, qd7);
            ffma2(acc[1][0], aa1, qd0); ffma2(acc[1][1], aa1, qd1);
            ffma2(acc[1][2], aa1, qd2); ffma2(acc[1][3], aa1, qd3);
            ffma2(acc[1][4], aa1, qd4); ffma2(acc[1][5], aa1, qd5);
            ffma2(acc[1][6], aa1, qd6); ffma2(acc[1][7], aa1, qd7);
            ffma2(acc[2][0], aa2, qd0); ffma2(acc[2][1], aa2, qd1);
            ffma2(acc[2][2], aa2, qd2); ffma2(acc[2][3], aa2, qd3);
            ffma2(acc[2][4], aa2, qd4); ffma2(acc[2][5], aa2, qd5);
            ffma2(acc[2][6], aa2, qd6); ffma2(acc[2][7], aa2, qd7);
            ffma2(acc[3][0], aa3, qd0); ffma2(acc[3][1], aa3, qd1);
            ffma2(acc[3][2], aa3, qd2); ffma2(acc[3][3], aa3, qd3);
            ffma2(acc[3][4], aa3, qd4); ffma2(acc[3][5], aa3, qd5);
            ffma2(acc[3][6], aa3, qd6); ffma2(acc[3][7], aa3, qd7);
        }
    }

    // ---- qnorm reduction ----
    __syncthreads();
    ssq[lk * 64 + ln] = myssq;
    __syncthreads();
    if (tid < 64) {
        float s2 = ssq[tid] + ssq[64 + tid] + ssq[128 + tid] + ssq[192 + tid];
        gN[tid] = fmaxf(sqrtf(s2), 1e-4f);
    }
    __syncthreads();

    const float NEG = __int_as_float(0xff800000);  // -inf

    float invn[8];
#pragma unroll
    for (int nn = 0; nn < 8; nn++) invn[nn] = 20.0f / gN[tx * 8 + nn];

    // ---- scale + mask, write dists tile to smem (overwrites As/Qs) ----
#pragma unroll
    for (int pp = 0; pp < 4; pp++) {
        int p = ty * 8 + pp * 2;
        int v0 = g_valid[p], v1 = g_valid[p + 1];
#pragma unroll
        for (int nn = 0; nn < 8; nn++) {
            unsigned long long v = acc[pp][nn];
            float lo = __uint_as_float((unsigned)v);
            float hi = __uint_as_float((unsigned)(v >> 32));
            int nl = tx * 8 + nn;
            dS[p * 64 + nl]       = v0 ? lo * invn[nn] : NEG;
            dS[(p + 1) * 64 + nl] = v1 ? hi * invn[nn] : NEG;
        }
    }
    __syncthreads();

    // ---- pass 1: max + argmax (first-index tie-break, matches jnp.argmax) ----
    int n = ln, qt = lk;
    float best = NEG; int bidx = qt * 64;
#pragma unroll 8
    for (int p = qt * 64; p < qt * 64 + 64; p++) {
        float d = dS[p * 64 + n];
        if (d > best) { best = d; bidx = p; }
    }
    rA[qt * 64 + n] = best; rI[qt * 64 + n] = bidx;
    __syncthreads();
    if (tid < 64) {
        float gb = NEG; int gi = 0;
#pragma unroll
        for (int q = 0; q < 4; q++) {
            float v = rA[q * 64 + tid];
            if (v > gb) { gb = v; gi = rI[q * 64 + tid]; }
        }
        gM[tid] = gb; gI[tid] = gi;
    }
    __syncthreads();

    // ---- pass 2: sumexp + weighted sum over valid protos ----
    float mx = gM[n];
    float se = 0.f, ws = 0.f;
#pragma unroll 8
    for (int p = qt * 64; p < qt * 64 + 64; p++) {
        float d = dS[p * 64 + n];
        if (d != NEG) { float e = expf(d - mx); se += e; ws = fmaf(e, d, ws); }
    }
    rS[qt * 64 + n] = se; rW[qt * 64 + n] = ws;
    __syncthreads();
    if (tid < 64) {
        float SE = rS[tid] + rS[64 + tid] + rS[128 + tid] + rS[192 + tid];
        float WS = rW[tid] + rW[64 + tid] + rW[128 + tid] + rW[192 + tid];
        size_t o = (size_t)b * NHW + n0 + tid;
        out[o]          = WS / SE;              // pred
        out[131072 + o] = (float)gI[tid];       // debug_assign
    }
}

// ---------------------------------------------------------------------------
// launch
// ---------------------------------------------------------------------------
#define SMEM_BYTES ((256 * 64 + 256 + 64 + 256 + 256 + 256 + 256 + 64 + 64) * 4)

extern "C" void kernel_launch(void* const* d_in, const int* in_sizes, int n_in,
                              void* d_out, int out_size) {
    const float* qry   = (const float*)d_in[0];
    const float* sup_x = (const float*)d_in[1];
    const float* sup_y = (const float*)d_in[2];
    float* out = (float*)d_out;

    cudaFuncSetAttribute(dist_kernel,
                         cudaFuncAttributeMaxDynamicSharedMemorySize, SMEM_BYTES);

    proto_kernel<<<256, 256>>>(sup_x, sup_y);
    grid_kernel<<<64, 256>>>(sup_y, out);
    dist_kernel<<<NBATCH * 64, 256, SMEM_BYTES>>>(qry, out);
}